// round 17
// baseline (speedup 1.0000x reference)
#include <cuda_runtime.h>
#include <cuda_fp16.h>
#include <cstdint>
#include <cstddef>

#define E_TOT 150000
#define TE    64          // rows per warp-group tile; CTA = 2 WGs = 128 rows
#define NT    256         // 8 warps = 2 warp-groups of 4
#define SA    136         // fp16 padded row stride (elements)
#define RB    272         // row bytes

// ---- smem layout (bytes) ----
#define OFF_VEC   0                      // 7 x 128 f32 = 3584
#define OFF_PART0 3584                   // 2 x 64 float2 = 1024
#define OFF_PART1 4608                   // 1024
#define OFF_A0    5632                   // 64*272 = 17408
#define OFF_A1    23040                  // 17408
#define OFF_W0    40448                  // 34816
#define OFF_W1    75264                  // 34816
#define SMEM_SZ   110080                 // -> 2 CTAs/SM

// pre-rounded weights: 27 matrices, fp16, padded layout identical to smem
__device__ __align__(16) __half g_w[27][128 * SA];
// pre-rounded x: fp16, linear [row][col]
__device__ __align__(16) __half g_x[(size_t)E_TOT * 128];

// ---------------------------------------------------------------------------
__device__ __forceinline__ uint32_t pkh(float a, float b) {
    __half2 t = __floats2half2_rn(a, b);
    return *(uint32_t*)&t;
}
__device__ __forceinline__ uint32_t s2u(const void* p) {
    uint32_t a;
    asm("{ .reg .u64 t; cvta.to.shared.u64 t, %1; cvt.u32.u64 %0, t; }" : "=r"(a) : "l"(p));
    return a;
}
__device__ __forceinline__ void cpa16(uint32_t saddr, const void* g) {
    asm volatile("cp.async.cg.shared.global [%0], [%1], 16;" :: "r"(saddr), "l"(g));
}
__device__ __forceinline__ void cpa_commit() { asm volatile("cp.async.commit_group;" ::: "memory"); }

#define BARS(id, n) asm volatile("bar.sync %0, %1;"   :: "r"(id), "r"(n) : "memory")
#define BARA(id, n) asm volatile("bar.arrive %0, %1;" :: "r"(id), "r"(n) : "memory")

__device__ __forceinline__ void mma16816(float d[4], const uint32_t a[4],
                                         uint32_t b0, uint32_t b1) {
    asm volatile(
        "mma.sync.aligned.m16n8k16.row.col.f32.f16.f16.f32 "
        "{%0,%1,%2,%3}, {%4,%5,%6,%7}, {%8,%9}, {%0,%1,%2,%3};\n"
        : "+f"(d[0]), "+f"(d[1]), "+f"(d[2]), "+f"(d[3])
        : "r"(a[0]), "r"(a[1]), "r"(a[2]), "r"(a[3]), "r"(b0), "r"(b1));
}
#define LDSM4(r, addr) \
    asm volatile("ldmatrix.sync.aligned.m8n8.x4.shared.b16 {%0,%1,%2,%3}, [%4];" \
        : "=r"((r)[0]), "=r"((r)[1]), "=r"((r)[2]), "=r"((r)[3]) : "r"(addr))

__device__ __forceinline__ float tanhf_fast(float x) {
    float r; asm("tanh.approx.f32 %0, %1;" : "=f"(r) : "f"(x)); return r;
}
__device__ __forceinline__ float silu(float y) {
    return y * fmaf(0.5f, tanhf_fast(0.5f * y), 0.5f);
}

// ---------------------------------------------------------------------------
// prep (single kernel): blocks [0,27) round weights; blocks [27,...) round x
// ---------------------------------------------------------------------------
__global__ void prep_all(const float* __restrict__ x,
                         const float* __restrict__ W1,
                         const float* __restrict__ ef2w, const float* __restrict__ f2w,
                         const float* __restrict__ ef3w, const float* __restrict__ f3w) {
    if (blockIdx.x < 27) {
        int m = blockIdx.x;
        const float* src;
        if (m < 9)       src = W1 + (size_t)m * 16384;
        else if (m < 18) { int b = m - 9;  src = b ? f2w + (size_t)(b - 1) * 16384 : ef2w; }
        else             { int b = m - 18; src = b ? f3w + (size_t)(b - 1) * 16384 : ef3w; }
        __half* w = g_w[m];
        for (int i = threadIdx.x; i < 16384; i += 256) {
            int r = i >> 7, c = i & 127;
            w[r * SA + c] = __float2half_rn(__ldg(src + i));
        }
        return;
    }
    size_t i = (size_t)(blockIdx.x - 27) * 256 + threadIdx.x;  // one float4 per thread
    if (i >= (size_t)E_TOT * 32) return;
    float4 v = __ldg((const float4*)x + i);
    uint2 uh;
    uh.x = pkh(v.x, v.y);
    uh.y = pkh(v.z, v.w);
    *(uint2*)(g_x + i * 4) = uh;
}

// ---------------------------------------------------------------------------
// 64x128x128 GEMM from smem via ldmatrix, m32n64 warp tiles:
// 4 warps = 2 m-groups (warp4>>1) x 2 n-groups (warp4&1).
// ---------------------------------------------------------------------------
__device__ __forceinline__ void gemm64(uint32_t abase, uint32_t wbase,
                                       float acc[2][8][4], int warp4, int lane) {
#pragma unroll
    for (int mi = 0; mi < 2; mi++)
#pragma unroll
        for (int nj = 0; nj < 8; nj++)
#pragma unroll
            for (int j = 0; j < 4; j++) acc[mi][nj][j] = 0.f;

    const int mblk = (warp4 >> 1) << 5;
    const int nblk = (warp4 & 1) << 6;

    const int rs_a = (lane & 7) + (((lane >> 3) & 1) << 3);
    const uint32_t ka = (lane >> 4) << 4;
    const uint32_t a0 = abase + (mblk + rs_a) * RB + ka;
    const uint32_t a1 = a0 + 16 * RB;
    const int rs_b = (lane & 7) + ((lane >> 4) << 3);
    const uint32_t kb = ((lane >> 3) & 1) << 4;
    const uint32_t bb = wbase + (nblk + rs_b) * RB + kb;

#pragma unroll 1
    for (int ks = 0; ks < 8; ks++) {
        const uint32_t k0b = ks << 5;
        uint32_t ah0[4], ah1[4];
        uint32_t bf[4][4];
        LDSM4(ah0, a0 + k0b);
        LDSM4(ah1, a1 + k0b);
#pragma unroll
        for (int p = 0; p < 4; p++)
            LDSM4(bf[p], bb + p * (16 * RB) + k0b);

#pragma unroll
        for (int p = 0; p < 4; p++) {
            mma16816(acc[0][2 * p],     ah0, bf[p][0], bf[p][1]);
            mma16816(acc[0][2 * p + 1], ah0, bf[p][2], bf[p][3]);
            mma16816(acc[1][2 * p],     ah1, bf[p][0], bf[p][1]);
            mma16816(acc[1][2 * p + 1], ah1, bf[p][2], bf[p][3]);
        }
    }
}

// ---------------------------------------------------------------------------
// stats: bias add + row sums; WG-local named barrier; returns m[], inv[].
// ---------------------------------------------------------------------------
__device__ __forceinline__ void epi_stats(char* sm, float acc[2][8][4], int vecb,
                                          int part_off, int barid,
                                          int warp4, int lane, float m[4], float inv[4]) {
    const int tig  = lane & 3;
    const int grp  = lane >> 2;
    const int ngrp = warp4 & 1;
    const int mblk = (warp4 >> 1) << 5;
    const int nblk = ngrp << 6;

    const float* bias = (const float*)(sm + OFF_VEC) + vecb * 128;

    float s[4] = {0.f, 0.f, 0.f, 0.f};
    float q[4] = {0.f, 0.f, 0.f, 0.f};
#pragma unroll
    for (int mi = 0; mi < 2; mi++) {
#pragma unroll
        for (int nj = 0; nj < 8; nj++) {
            const int c = nblk + (nj << 3) + (tig << 1);
            const float b0 = bias[c], b1 = bias[c + 1];
            float* a = acc[mi][nj];
            a[0] += b0; a[1] += b1; a[2] += b0; a[3] += b1;
            s[2 * mi]     += a[0] + a[1];
            q[2 * mi]      = fmaf(a[0], a[0], fmaf(a[1], a[1], q[2 * mi]));
            s[2 * mi + 1] += a[2] + a[3];
            q[2 * mi + 1]  = fmaf(a[2], a[2], fmaf(a[3], a[3], q[2 * mi + 1]));
        }
    }
#pragma unroll
    for (int off = 1; off <= 2; off <<= 1) {
#pragma unroll
        for (int i = 0; i < 4; i++) {
            s[i] += __shfl_xor_sync(0xFFFFFFFFu, s[i], off);
            q[i] += __shfl_xor_sync(0xFFFFFFFFu, q[i], off);
        }
    }
    float2* part = (float2*)(sm + part_off);
    if (tig == 0) {
        part[ngrp * 64 + mblk + grp]      = make_float2(s[0], q[0]);
        part[ngrp * 64 + mblk + grp + 8]  = make_float2(s[1], q[1]);
        part[ngrp * 64 + mblk + grp + 16] = make_float2(s[2], q[2]);
        part[ngrp * 64 + mblk + grp + 24] = make_float2(s[3], q[3]);
    }
    BARS(barid, 128);
#pragma unroll
    for (int i = 0; i < 4; i++) {
        const int row = mblk + grp + (i << 3);
        float2 p0 = part[row];
        float2 p1 = part[64 + row];
        const float ss = p0.x + p1.x, qq = p0.y + p1.y;
        m[i]   = ss * (1.0f / 128.0f);
        inv[i] = rsqrtf(fmaf(-m[i], m[i], qq * (1.0f / 128.0f)) + 1e-5f);
    }
}

// ---------------------------------------------------------------------------
// normalize + SiLU + fp16 store into WG act buffer
// ---------------------------------------------------------------------------
__device__ __forceinline__ void epi_norm(char* sm, float acc[2][8][4], int vecb,
                                         int a_off, const float m[4], const float inv[4],
                                         int warp4, int lane) {
    const int tig  = lane & 3;
    const int grp  = lane >> 2;
    const int mblk = (warp4 >> 1) << 5;
    const int nblk = (warp4 & 1) << 6;

    const float* vec = (const float*)(sm + OFF_VEC);
    const float* lw  = vec + vecb * 128 + 128;
    const float* lb  = lw + 128;

#pragma unroll
    for (int mi = 0; mi < 2; mi++) {
        const int i0 = 2 * mi, i1 = 2 * mi + 1;
        const int r0 = mblk + grp + (mi << 4);
        const int r1 = r0 + 8;
#pragma unroll
        for (int nj = 0; nj < 8; nj++) {
            const int c = nblk + (nj << 3) + (tig << 1);
            const float w0 = lw[c], w1 = lw[c + 1], c0 = lb[c], c1 = lb[c + 1];
            const float* a = acc[mi][nj];
            float y00 = silu((a[0] - m[i0]) * inv[i0] * w0 + c0);
            float y01 = silu((a[1] - m[i0]) * inv[i0] * w1 + c1);
            float y10 = silu((a[2] - m[i1]) * inv[i1] * w0 + c0);
            float y11 = silu((a[3] - m[i1]) * inv[i1] * w1 + c1);
            *(uint32_t*)(sm + a_off + r0 * RB + c * 2) = pkh(y00, y01);
            *(uint32_t*)(sm + a_off + r1 * RB + c * 2) = pkh(y10, y11);
        }
    }
}

__device__ __forceinline__ void out_store(char* sm, float acc[2][8][4],
                                          float* __restrict__ out, size_t obase,
                                          int nvalid, int warp4, int lane) {
    const int tig  = lane & 3;
    const int grp  = lane >> 2;
    const int mblk = (warp4 >> 1) << 5;
    const int nblk = (warp4 & 1) << 6;
    const float* bias = (const float*)(sm + OFF_VEC) + 6 * 128;
#pragma unroll
    for (int mi = 0; mi < 2; mi++) {
        const int r0 = mblk + grp + (mi << 4);
        const int r1 = r0 + 8;
        float* o0 = out + obase + (size_t)r0 * 128;
        float* o1 = o0 + (size_t)8 * 128;
#pragma unroll
        for (int nj = 0; nj < 8; nj++) {
            const int c = nblk + (nj << 3) + (tig << 1);
            const float b0 = bias[c], b1 = bias[c + 1];
            const float* a = acc[mi][nj];
            if (r0 < nvalid)
                *(float2*)(o0 + c) = make_float2(a[0] + b0, a[1] + b1);
            if (r1 < nvalid)
                *(float2*)(o1 + c) = make_float2(a[2] + b0, a[3] + b1);
        }
    }
}

__device__ __forceinline__ void cp_w(uint32_t sdst, int m, int t, int nth) {
    const char* g = (const char*)g_w[m];               // 34816B fp16
    for (int i = t; i < 34816 / 16; i += nth)
        cpa16(sdst + i * 16, g + (size_t)i * 16);
    cpa_commit();
}

// ---------------------------------------------------------------------------
extern __shared__ char smraw[];

__global__ void __launch_bounds__(NT, 2)
urmlp_kernel(const float* __restrict__ b1c,
             const float* __restrict__ eln1w, const float* __restrict__ eln1b,
             const float* __restrict__ ef2b,
             const float* __restrict__ eln2w, const float* __restrict__ eln2b,
             const float* __restrict__ ef3b,
             const float* __restrict__ ln1w,  const float* __restrict__ ln1b,
             const float* __restrict__ f2b,
             const float* __restrict__ ln2w,  const float* __restrict__ ln2b,
             const float* __restrict__ f3b,
             float* __restrict__ out)
{
    char* sm = smraw;
    const int tid   = threadIdx.x;
    const int wg    = tid >> 7;          // warp-group 0/1
    const int wtid  = tid & 127;
    const int warp4 = wtid >> 5;
    const int lane  = tid & 31;
    const int barid = 1 + wg;            // WG-local named barrier
    const int bid  = blockIdx.x;
    const int pair = bid / 9;
    const int br   = bid - pair * 9;
    const int base = pair * 128 + wg * TE;
    const int nval = min(TE, E_TOT - base);
    const uint32_t sb = s2u(sm);
    const int a_off = wg ? OFF_A1 : OFF_A0;
    const int p_off = wg ? OFF_PART1 : OFF_PART0;
    const uint32_t abase = sb + a_off;

    // init loads (all threads): W1 -> buf0, W2 -> buf1; each WG its x tile
    cp_w(sb + OFF_W0, br, tid, NT);
    cp_w(sb + OFF_W1, 9 + br, tid, NT);
    {
        for (int i = wtid; i < TE * 16; i += 128) {
            const int row = i >> 4, ch = i & 15;
            const uint32_t dh = sb + a_off + row * RB + ch * 16;
            if (row < nval) {
                cpa16(dh, g_x + (size_t)(base + row) * 128 + ch * 8);
            } else {
                *(uint4*)(sm + a_off + row * RB + ch * 16) = make_uint4(0, 0, 0, 0);
            }
        }
        cpa_commit();
    }

    // per-branch vectors: [b1, lw1, lb1, b2, lw2, lb2, b3]
    if (tid < 128) {
        float* vec = (float*)(sm + OFF_VEC);
        const float* s0 = b1c + br * 128;
        const float* s1 = br ? ln1w + (br - 1) * 128 : eln1w;
        const float* s2 = br ? ln1b + (br - 1) * 128 : eln1b;
        const float* s3 = br ? f2b  + (br - 1) * 128 : ef2b;
        const float* s4 = br ? ln2w + (br - 1) * 128 : eln2w;
        const float* s5 = br ? ln2b + (br - 1) * 128 : eln2b;
        const float* s6 = br ? f3b  + (br - 1) * 128 : ef3b;
        vec[0 * 128 + tid] = __ldg(s0 + tid);
        vec[1 * 128 + tid] = __ldg(s1 + tid);
        vec[2 * 128 + tid] = __ldg(s2 + tid);
        vec[3 * 128 + tid] = __ldg(s3 + tid);
        vec[4 * 128 + tid] = __ldg(s4 + tid);
        vec[5 * 128 + tid] = __ldg(s5 + tid);
        vec[6 * 128 + tid] = __ldg(s6 + tid);
    }

    asm volatile("cp.async.wait_group 0;" ::: "memory");
    __syncthreads();                                    // S0

    float acc[2][8][4];
    float m[4], inv[4];

    // ================= stage 1 (W1, buf0) =================
    gemm64(abase, sb + OFF_W0, acc, warp4, lane);
    if (wg == 1) {
        BARA(3, 256);                                   // WG1: buf0 reads done
    } else {
        BARS(3, 256);                                   // WG0: wait both WGs done with buf0
        cp_w(sb + OFF_W0, 18 + br, wtid, 128);          // W3 -> buf0 (WG0 only)
    }
    epi_stats(sm, acc, 0, p_off, barid, warp4, lane, m, inv);
    epi_norm(sm, acc, 0, a_off, m, inv, warp4, lane);
    BARS(barid, 128);                                   // act visible within WG

    // ================= stage 2 (W2, buf1) =================
    gemm64(abase, sb + OFF_W1, acc, warp4, lane);
    epi_stats(sm, acc, 3, p_off, barid, warp4, lane, m, inv);
    epi_norm(sm, acc, 3, a_off, m, inv, warp4, lane);
    if (wg == 0)
        asm volatile("cp.async.wait_group 0;" ::: "memory");  // W3 landed
    BARS(4, 256);                                       // W3 + act visible to all

    // ================= stage 3 (W3, buf0) -> out =================
    gemm64(abase, sb + OFF_W0, acc, warp4, lane);
    out_store(sm, acc, out, ((size_t)br * E_TOT + base) * 128, nval, warp4, lane);
}

extern "C" void kernel_launch(void* const* d_in, const int* in_sizes, int n_in,
                              void* d_out, int out_size) {
    const float* x     = (const float*)d_in[0];
    const float* W1    = (const float*)d_in[1];
    const float* b1    = (const float*)d_in[2];
    const float* eln1w = (const float*)d_in[3];
    const float* eln1b = (const float*)d_in[4];
    const float* ef2w  = (const float*)d_in[5];
    const float* ef2b  = (const float*)d_in[6];
    const float* eln2w = (const float*)d_in[7];
    const float* eln2b = (const float*)d_in[8];
    const float* ef3w  = (const float*)d_in[9];
    const float* ef3b  = (const float*)d_in[10];
    const float* ln1w  = (const float*)d_in[11];
    const float* ln1b  = (const float*)d_in[12];
    const float* f2w   = (const float*)d_in[13];
    const float* f2b   = (const float*)d_in[14];
    const float* ln2w  = (const float*)d_in[15];
    const float* ln2b  = (const float*)d_in[16];
    const float* f3w   = (const float*)d_in[17];
    const float* f3b   = (const float*)d_in[18];
    float* out = (float*)d_out;

    cudaFuncSetAttribute(urmlp_kernel, cudaFuncAttributeMaxDynamicSharedMemorySize, SMEM_SZ);

    const int xblocks = (E_TOT * 32 + 255) / 256;
    prep_all<<<27 + xblocks, 256>>>(x, W1, ef2w, f2w, ef3w, f3w);

    const int pairs = (E_TOT + 127) / 128;   // 1172
    urmlp_kernel<<<pairs * 9, NT, SMEM_SZ>>>(
        b1, eln1w, eln1b, ef2b, eln2w, eln2b, ef3b,
        ln1w, ln1b, f2b, ln2w, ln2b, f3b, out);
}